// round 13
// baseline (speedup 1.0000x reference)
#include <cuda_runtime.h>
#include <cuda.h>
#include <cstdint>

#define B_   8
#define T_   316
#define CIN_ 64
#define HF_  128
#define G_   32
#define E_   384

#define N_PATCHES (B_*T_*CIN_*64)
#define N_BT      (B_*T_)

#define FMAP_BLOCKS  (B_ * G_ * 4)       // (batch, grid-row, e-quarter)
#define DMA_BLOCKS   (T_ * 2)            // (token-index, cin-half)
#define EQ_          96
#define SMS_         97

#define IMG_STRIDE4  (HF_ * HF_ / 4)     // float4 stride between cin planes

// half-token crop tile: 32 cins * 8 rows * 8 cols * 4B = 8 KB, double buffered
#define TILE_BYTES   8192
#define SMEM_DYN     (2 * TILE_BYTES + 128)

// ---------------------------------------------------------------------------
__device__ __forceinline__ uint32_t smem_u32(const void* p) {
    uint32_t a;
    asm("{ .reg .u64 t; cvta.to.shared.u64 t, %1; cvt.u32.u64 %0, t; }"
        : "=r"(a) : "l"(p));
    return a;
}

__device__ __forceinline__ void mbar_wait(uint32_t mbar, int phase) {
    asm volatile(
        "{\n\t"
        ".reg .pred P1;\n\t"
        "WAIT_LOOP_%=:\n\t"
        "mbarrier.try_wait.parity.acquire.cta.shared::cta.b64 P1, [%0], %1, 0x989680;\n\t"
        "@P1 bra.uni WAIT_DONE_%=;\n\t"
        "bra.uni WAIT_LOOP_%=;\n\t"
        "WAIT_DONE_%=:\n\t"
        "}"
        :: "r"(mbar), "r"(phase) : "memory");
}

// ---------------------------------------------------------------------------
// Single fused kernel.
//   blocks [0, FMAP_BLOCKS):        fmap transpose-gather
//   blocks [+DMA_BLOCKS):           p16 crop DMA, depth-2 pipelined over the
//                                   8 batches of one (token-idx, cin-half)
//   blocks [+N_BT):                 per-token meta + p8 bilinear compute
// ---------------------------------------------------------------------------
__global__ void __launch_bounds__(256) fused_kernel(
        const float* __restrict__ x_in,
        const float* __restrict__ tokens,
        const int*   __restrict__ metas,
        float* __restrict__ patches,
        float* __restrict__ cx,
        float* __restrict__ cy,
        float* __restrict__ sc,
        float* __restrict__ fmap,
        const __grid_constant__ CUtensorMap tmap) {

    extern __shared__ char smem_raw[];
    int tid = threadIdx.x;

    if (blockIdx.x >= FMAP_BLOCKS + DMA_BLOCKS) {
        // ------------------- per-token meta + p8 compute -------------------
        int tok = blockIdx.x - FMAP_BLOCKS - DMA_BLOCKS;
        int b   = tok / T_;

        const int* m = metas + (size_t)tok * 5;
        int r = __ldg(&m[0]), c = __ldg(&m[1]), p = __ldg(&m[3]);

        if (tid == 0) {
            int span = __ldg(&m[2]);
            float hs = 0.5f * (float)span;
            cx[tok] = (float)c + hs;
            cy[tok] = (float)r + hs;
            sc[tok] = (p == 16) ? 1.0f : ((p == 8) ? 2.0f : 0.0f);
        }
        if (p == 16) return;   // DMA blocks handle the crop

        int half = tid & 1;
        int i    = (tid >> 1) & 7;
        int cin0 = tid >> 4;             // 0..15 ; cin = cin0 + 16k

        const float4* img4 = (const float4*)x_in +
                             ((size_t)b * CIN_ + cin0) * IMG_STRIDE4;
        float4* dst = ((float4*)patches) + (size_t)tok * 1024 + tid;

        if (p > 0) {
            int pf = p >> 1; if (pf < 1) pf = 1;     // <= 4 here
            float pff   = (float)pf;
            float scale = pff * 0.125f;
            float hi    = pff - 1.0f;

            float rel_i = fminf(fmaxf(((float)i + 0.5f) * scale - 0.5f, 0.0f), hi);
            float i0f = floorf(rel_i);
            float wy  = rel_i - i0f;
            float i1f = fminf(i0f + 1.0f, hi);
            int y0off = (r * 4 + (int)i0f) * 32 + c;
            int y1off = (r * 4 + (int)i1f) * 32 + c;

            int   j0[4], j1[4];
            float wx[4];
            #pragma unroll
            for (int jj = 0; jj < 4; jj++) {
                float j = (float)(half * 4 + jj);
                float rel_j = fminf(fmaxf((j + 0.5f) * scale - 0.5f, 0.0f), hi);
                float j0f = floorf(rel_j);
                wx[jj] = rel_j - j0f;
                j0[jj] = (int)j0f;
                int t1 = j0[jj] + 1; if (t1 > (int)hi) t1 = (int)hi;
                j1[jj] = t1;
            }

            float4 t0[4], t1[4];
            #pragma unroll
            for (int k = 0; k < 4; k++) {
                const float4* ik = img4 + (size_t)k * 16 * IMG_STRIDE4;
                t0[k] = __ldg(ik + y0off);
                t1[k] = __ldg(ik + y1off);
            }
            #pragma unroll
            for (int k = 0; k < 4; k++) {
                float rb[4];
                rb[0] = t0[k].x + (t1[k].x - t0[k].x) * wy;
                rb[1] = t0[k].y + (t1[k].y - t0[k].y) * wy;
                rb[2] = t0[k].z + (t1[k].z - t0[k].z) * wy;
                rb[3] = t0[k].w + (t1[k].w - t0[k].w) * wy;
                float4 o;
                o.x = rb[j0[0]] + (rb[j1[0]] - rb[j0[0]]) * wx[0];
                o.y = rb[j0[1]] + (rb[j1[1]] - rb[j0[1]]) * wx[1];
                o.z = rb[j0[2]] + (rb[j1[2]] - rb[j0[2]]) * wx[2];
                o.w = rb[j0[3]] + (rb[j1[3]] - rb[j0[3]]) * wx[3];
                __stcs(dst + k * 256, o);
            }
        } else {
            float4 z = make_float4(0.f, 0.f, 0.f, 0.f);
            #pragma unroll
            for (int k = 0; k < 4; k++) __stcs(dst + k * 256, z);
        }
        return;
    }

    if (blockIdx.x >= FMAP_BLOCKS) {
        // ----------------------- p16 DMA (pipelined) -----------------------
        if (tid != 0) return;
        int d = blockIdx.x - FMAP_BLOCKS;
        int t = d >> 1;
        int h = d & 1;

        // collect p16 tiles across batches
        int bs[B_], rs[B_], cs[B_];
        int cnt = 0;
        #pragma unroll
        for (int b = 0; b < B_; b++) {
            const int* m = metas + (size_t)(b * T_ + t) * 5;
            if (__ldg(&m[3]) == 16) {
                bs[cnt] = b; rs[cnt] = __ldg(&m[0]); cs[cnt] = __ldg(&m[1]);
                cnt++;
            }
        }
        if (cnt == 0) return;

        uint32_t sbase = smem_u32(smem_raw);
        uint32_t buf[2]  = { sbase, sbase + TILE_BYTES };
        uint32_t mbar[2] = { sbase + 2 * TILE_BYTES, sbase + 2 * TILE_BYTES + 8 };
        int ph[2] = { 0, 0 };

        asm volatile("mbarrier.init.shared.b64 [%0], 1;" :: "r"(mbar[0]) : "memory");
        asm volatile("mbarrier.init.shared.b64 [%0], 1;" :: "r"(mbar[1]) : "memory");
        asm volatile("fence.proxy.async.shared::cta;" ::: "memory");

        // pre-issue load 0
        asm volatile("mbarrier.arrive.expect_tx.shared.b64 _, [%0], %1;"
                     :: "r"(mbar[0]), "r"(TILE_BYTES) : "memory");
        asm volatile(
            "cp.async.bulk.tensor.3d.shared::cta.global.tile.mbarrier::complete_tx::bytes "
            "[%0], [%1, {%2, %3, %4}], [%5];"
            :: "r"(buf[0]), "l"(&tmap),
               "r"(cs[0] * 4), "r"(rs[0] * 4), "r"(bs[0] * CIN_ + h * 32),
               "r"(mbar[0]) : "memory");

        for (int i = 0; i < cnt; i++) {
            int s = i & 1;
            mbar_wait(mbar[s], ph[s]);
            ph[s] ^= 1;

            asm volatile("fence.proxy.async.shared::cta;" ::: "memory");
            char* gdst = (char*)patches +
                         ((size_t)(bs[i] * T_ + t)) * 16384 + (size_t)h * TILE_BYTES;
            asm volatile(
                "cp.async.bulk.global.shared::cta.bulk_group [%0], [%1], %2;"
                :: "l"(gdst), "r"(buf[s]), "r"(TILE_BYTES) : "memory");
            asm volatile("cp.async.bulk.commit_group;" ::: "memory");

            if (i + 1 < cnt) {
                // buffer 1-s was last stored at iteration i-1; ensure drained
                asm volatile("cp.async.bulk.wait_group 1;" ::: "memory");
                int ns = 1 - s;
                asm volatile("mbarrier.arrive.expect_tx.shared.b64 _, [%0], %1;"
                             :: "r"(mbar[ns]), "r"(TILE_BYTES) : "memory");
                asm volatile(
                    "cp.async.bulk.tensor.3d.shared::cta.global.tile.mbarrier::complete_tx::bytes "
                    "[%0], [%1, {%2, %3, %4}], [%5];"
                    :: "r"(buf[ns]), "l"(&tmap),
                       "r"(cs[i+1] * 4), "r"(rs[i+1] * 4),
                       "r"(bs[i+1] * CIN_ + h * 32),
                       "r"(mbar[ns]) : "memory");
            }
        }
        asm volatile("cp.async.bulk.wait_group 0;" ::: "memory");
        return;
    }

    // ----------------------------- fmap -----------------------------
    float* sm    = (float*)smem_raw;                       // 32*SMS_ floats
    int*   s_own = (int*)(smem_raw + 32 * SMS_ * 4);       // 32 ints

    int fb  = blockIdx.x;
    int q   = fb & 3;              // e-quarter
    int row = (fb >> 2) & 31;      // grid row
    int b   = fb >> 7;             // batch
    int lane = tid & 31;
    int w    = tid >> 5;

    // owners for this grid row, from metas (coverage is exact, no races)
    for (int t = tid; t < T_; t += 256) {
        const int* m = metas + (size_t)(b * T_ + t) * 5;
        int r = m[0], c = m[1], span = m[2], p = m[3];
        int di = row - r;
        if (p > 0 && di >= 0 && di < span) {
            for (int dc = 0; dc < span; dc++) {
                int col = c + dc;
                if (col >= 0 && col < G_) s_own[col] = t;
            }
        }
    }
    __syncthreads();

    // phase 1: coalesced token loads -> smem
    int e0 = q * EQ_;
    #pragma unroll
    for (int cc = 0; cc < 4; cc++) {
        int cell = w * 4 + cc;
        const float* src = tokens + ((size_t)(b * T_ + s_own[cell])) * E_ + e0;
        #pragma unroll
        for (int it = 0; it < 3; it++) {
            int e = it * 32 + lane;
            sm[cell * SMS_ + e] = __ldg(&src[e]);
        }
    }
    __syncthreads();

    // phase 2: lane = cell -> fully coalesced 128B stores
    float* dstb = fmap + ((size_t)(b * E_ + e0) + w * 12) * (G_ * G_)
                       + row * 32 + lane;
    #pragma unroll
    for (int k = 0; k < 12; k++)
        __stcs(&dstb[(size_t)k * (G_ * G_)], sm[lane * SMS_ + w * 12 + k]);
}

// ---------------------------------------------------------------------------
typedef CUresult (*TmapEncodeFn)(
    CUtensorMap*, CUtensorMapDataType, cuuint32_t, void*,
    const cuuint64_t*, const cuuint64_t*, const cuuint32_t*, const cuuint32_t*,
    CUtensorMapInterleave, CUtensorMapSwizzle, CUtensorMapL2promotion,
    CUtensorMapFloatOOBfill);

extern "C" void kernel_launch(void* const* d_in, const int* in_sizes, int n_in,
                              void* d_out, int out_size) {
    const float* x_in   = (const float*)d_in[0];
    const float* tokens = (const float*)d_in[1];
    const int*   metas  = (const int*)d_in[2];

    float* out     = (float*)d_out;
    float* patches = out;
    float* cx      = out + (size_t)N_PATCHES;
    float* cy      = cx + N_BT;
    float* sc      = cy + N_BT;
    float* fmap    = sc + N_BT;

    static TmapEncodeFn tmap_encode = nullptr;
    if (!tmap_encode) {
        cudaDriverEntryPointQueryResult st;
        cudaGetDriverEntryPointByVersion(
            "cuTensorMapEncodeTiled", (void**)&tmap_encode, 12000,
            cudaEnableDefault, &st);
    }

    CUtensorMap tmap;
    {
        cuuint64_t dims[3]    = {HF_, HF_, (cuuint64_t)B_ * CIN_};
        cuuint64_t strides[2] = {HF_ * 4, (cuuint64_t)HF_ * HF_ * 4};
        cuuint32_t box[3]     = {8, 8, 32};     // 8 cols x 8 rows x 32 cins = 8KB
        cuuint32_t es[3]      = {1, 1, 1};
        tmap_encode(&tmap, CU_TENSOR_MAP_DATA_TYPE_FLOAT32, 3, (void*)x_in,
                    dims, strides, box, es,
                    CU_TENSOR_MAP_INTERLEAVE_NONE, CU_TENSOR_MAP_SWIZZLE_NONE,
                    CU_TENSOR_MAP_L2_PROMOTION_L2_128B,
                    CU_TENSOR_MAP_FLOAT_OOB_FILL_NONE);
    }

    fused_kernel<<<FMAP_BLOCKS + DMA_BLOCKS + N_BT, 256, SMEM_DYN>>>(
        x_in, tokens, metas, patches, cx, cy, sc, fmap, tmap);
}

// round 14
// speedup vs baseline: 1.0835x; 1.0835x over previous
#include <cuda_runtime.h>
#include <cuda.h>
#include <cstdint>

#define B_   8
#define T_   316
#define CIN_ 64
#define HF_  128
#define G_   32
#define E_   384

#define N_PATCHES (B_*T_*CIN_*64)
#define N_BT      (B_*T_)

#define FMAP_BLOCKS  (B_ * G_ * 4)       // (batch, grid-row, e-quarter)
#define DMA_BLOCKS   (N_BT * 2)          // (token, cin-half), exits unless p==16
#define EQ_          96
#define SMS_         97

#define IMG_STRIDE4  (HF_ * HF_ / 4)     // float4 stride between cin planes

// half-token crop tile: 32 cins * 8 rows * 8 cols * 4B = 8 KB
#define TILE_BYTES   8192
// dynamic smem must also fit the fmap path: 32*97*4 + 32*4 = 12544
#define SMEM_DYN     13056

// ---------------------------------------------------------------------------
__device__ __forceinline__ uint32_t smem_u32(const void* p) {
    uint32_t a;
    asm("{ .reg .u64 t; cvta.to.shared.u64 t, %1; cvt.u32.u64 %0, t; }"
        : "=r"(a) : "l"(p));
    return a;
}

// ---------------------------------------------------------------------------
// Single fused kernel, three segments:
//   [0, FMAP_BLOCKS)           : fmap transpose-gather
//   [+DMA_BLOCKS)              : p16 crop DMA per (token, cin-half)
//                                (8KB TMA load -> smem -> 8KB bulk store)
//   [+N_BT)                    : per-token meta + p8 bilinear compute
//                                (4 float4/thread, R9 best shape)
// ---------------------------------------------------------------------------
__global__ void __launch_bounds__(256) fused_kernel(
        const float* __restrict__ x_in,
        const float* __restrict__ tokens,
        const int*   __restrict__ metas,
        float* __restrict__ patches,
        float* __restrict__ cx,
        float* __restrict__ cy,
        float* __restrict__ sc,
        float* __restrict__ fmap,
        const __grid_constant__ CUtensorMap tmap) {

    extern __shared__ char smem_raw[];
    int tid = threadIdx.x;

    if (blockIdx.x >= FMAP_BLOCKS + DMA_BLOCKS) {
        // ------------------- per-token meta + p8 compute -------------------
        int tok = blockIdx.x - FMAP_BLOCKS - DMA_BLOCKS;
        int b   = tok / T_;

        const int* m = metas + (size_t)tok * 5;
        int r = __ldg(&m[0]), c = __ldg(&m[1]), p = __ldg(&m[3]);

        if (tid == 0) {
            int span = __ldg(&m[2]);
            float hs = 0.5f * (float)span;
            cx[tok] = (float)c + hs;
            cy[tok] = (float)r + hs;
            sc[tok] = (p == 16) ? 1.0f : ((p == 8) ? 2.0f : 0.0f);
        }
        if (p == 16) return;   // DMA blocks handle the crop

        // decode (invariant in k): half = bit0, i = bits1-3, cin0 = bits4-7
        int half = tid & 1;
        int i    = (tid >> 1) & 7;
        int cin0 = tid >> 4;             // 0..15 ; cin = cin0 + 16k

        const float4* img4 = (const float4*)x_in +
                             ((size_t)b * CIN_ + cin0) * IMG_STRIDE4;
        float4* dst = ((float4*)patches) + (size_t)tok * 1024 + tid;

        if (p > 0) {
            int pf = p >> 1; if (pf < 1) pf = 1;     // <= 4 here
            float pff   = (float)pf;
            float scale = pff * 0.125f;
            float hi    = pff - 1.0f;

            float rel_i = fminf(fmaxf(((float)i + 0.5f) * scale - 0.5f, 0.0f), hi);
            float i0f = floorf(rel_i);
            float wy  = rel_i - i0f;
            float i1f = fminf(i0f + 1.0f, hi);
            int y0off = (r * 4 + (int)i0f) * 32 + c;
            int y1off = (r * 4 + (int)i1f) * 32 + c;

            int   j0[4], j1[4];
            float wx[4];
            #pragma unroll
            for (int jj = 0; jj < 4; jj++) {
                float j = (float)(half * 4 + jj);
                float rel_j = fminf(fmaxf((j + 0.5f) * scale - 0.5f, 0.0f), hi);
                float j0f = floorf(rel_j);
                wx[jj] = rel_j - j0f;
                j0[jj] = (int)j0f;
                int t1 = j0[jj] + 1; if (t1 > (int)hi) t1 = (int)hi;
                j1[jj] = t1;
            }

            float4 t0[4], t1[4];
            #pragma unroll
            for (int k = 0; k < 4; k++) {
                const float4* ik = img4 + (size_t)k * 16 * IMG_STRIDE4;
                t0[k] = __ldg(ik + y0off);
                t1[k] = __ldg(ik + y1off);
            }
            #pragma unroll
            for (int k = 0; k < 4; k++) {
                float rb[4];
                rb[0] = t0[k].x + (t1[k].x - t0[k].x) * wy;
                rb[1] = t0[k].y + (t1[k].y - t0[k].y) * wy;
                rb[2] = t0[k].z + (t1[k].z - t0[k].z) * wy;
                rb[3] = t0[k].w + (t1[k].w - t0[k].w) * wy;
                float4 o;
                o.x = rb[j0[0]] + (rb[j1[0]] - rb[j0[0]]) * wx[0];
                o.y = rb[j0[1]] + (rb[j1[1]] - rb[j0[1]]) * wx[1];
                o.z = rb[j0[2]] + (rb[j1[2]] - rb[j0[2]]) * wx[2];
                o.w = rb[j0[3]] + (rb[j1[3]] - rb[j0[3]]) * wx[3];
                __stcs(dst + k * 256, o);
            }
        } else {
            float4 z = make_float4(0.f, 0.f, 0.f, 0.f);
            #pragma unroll
            for (int k = 0; k < 4; k++) __stcs(dst + k * 256, z);
        }
        return;
    }

    if (blockIdx.x >= FMAP_BLOCKS) {
        // ----------------------- p16 DMA -----------------------
        int pid = blockIdx.x - FMAP_BLOCKS;
        int tok = pid >> 1;
        int h   = pid & 1;                 // cin half
        int b   = tok / T_;

        const int* m = metas + (size_t)tok * 5;
        if (__ldg(&m[3]) != 16) return;
        int r = __ldg(&m[0]), c = __ldg(&m[1]);

        if (tid == 0) {
            uint32_t sbase = smem_u32(smem_raw);
            uint32_t mbar  = sbase + TILE_BYTES;

            asm volatile("mbarrier.init.shared.b64 [%0], 1;"
                         :: "r"(mbar) : "memory");
            asm volatile("fence.proxy.async.shared::cta;" ::: "memory");
            asm volatile("mbarrier.arrive.expect_tx.shared.b64 _, [%0], %1;"
                         :: "r"(mbar), "r"(TILE_BYTES) : "memory");

            int xcoord = c * 4;               // +8 <= 128
            int ycoord = r * 4;               // +8 <= 128
            int zcoord = b * CIN_ + h * 32;   // +32 <= 512
            asm volatile(
                "cp.async.bulk.tensor.3d.shared::cta.global.tile.mbarrier::complete_tx::bytes "
                "[%0], [%1, {%2, %3, %4}], [%5];"
                :: "r"(sbase), "l"(&tmap),
                   "r"(xcoord), "r"(ycoord), "r"(zcoord),
                   "r"(mbar) : "memory");

            // wait for load completion (parity 0)
            asm volatile(
                "{\n\t"
                ".reg .pred P1;\n\t"
                "WAIT_LOOP_%=:\n\t"
                "mbarrier.try_wait.parity.acquire.cta.shared::cta.b64 P1, [%0], 0, 0x989680;\n\t"
                "@P1 bra.uni WAIT_DONE_%=;\n\t"
                "bra.uni WAIT_LOOP_%=;\n\t"
                "WAIT_DONE_%=:\n\t"
                "}"
                :: "r"(mbar) : "memory");

            asm volatile("fence.proxy.async.shared::cta;" ::: "memory");

            // smem layout [cin][i][8 floats] == patches layout: flat copy
            char* gdst = (char*)patches + (size_t)tok * 16384 + (size_t)h * TILE_BYTES;
            asm volatile(
                "cp.async.bulk.global.shared::cta.bulk_group [%0], [%1], %2;"
                :: "l"(gdst), "r"(sbase), "r"(TILE_BYTES) : "memory");
            asm volatile("cp.async.bulk.commit_group;" ::: "memory");
            asm volatile("cp.async.bulk.wait_group 0;" ::: "memory");
        }
        return;
    }

    // ----------------------------- fmap -----------------------------
    float* sm    = (float*)smem_raw;                       // 32*SMS_ floats
    int*   s_own = (int*)(smem_raw + 32 * SMS_ * 4);       // 32 ints

    int fb  = blockIdx.x;
    int q   = fb & 3;              // e-quarter
    int row = (fb >> 2) & 31;      // grid row
    int b   = fb >> 7;             // batch
    int lane = tid & 31;
    int w    = tid >> 5;

    // owners for this grid row, from metas (coverage is exact, no races)
    for (int t = tid; t < T_; t += 256) {
        const int* m = metas + (size_t)(b * T_ + t) * 5;
        int r = m[0], c = m[1], span = m[2], p = m[3];
        int di = row - r;
        if (p > 0 && di >= 0 && di < span) {
            for (int dc = 0; dc < span; dc++) {
                int col = c + dc;
                if (col >= 0 && col < G_) s_own[col] = t;
            }
        }
    }
    __syncthreads();

    // phase 1: coalesced token loads -> smem
    int e0 = q * EQ_;
    #pragma unroll
    for (int cc = 0; cc < 4; cc++) {
        int cell = w * 4 + cc;
        const float* src = tokens + ((size_t)(b * T_ + s_own[cell])) * E_ + e0;
        #pragma unroll
        for (int it = 0; it < 3; it++) {
            int e = it * 32 + lane;
            sm[cell * SMS_ + e] = __ldg(&src[e]);
        }
    }
    __syncthreads();

    // phase 2: lane = cell -> fully coalesced 128B stores
    float* dstb = fmap + ((size_t)(b * E_ + e0) + w * 12) * (G_ * G_)
                       + row * 32 + lane;
    #pragma unroll
    for (int k = 0; k < 12; k++)
        __stcs(&dstb[(size_t)k * (G_ * G_)], sm[lane * SMS_ + w * 12 + k]);
}

// ---------------------------------------------------------------------------
typedef CUresult (*TmapEncodeFn)(
    CUtensorMap*, CUtensorMapDataType, cuuint32_t, void*,
    const cuuint64_t*, const cuuint64_t*, const cuuint32_t*, const cuuint32_t*,
    CUtensorMapInterleave, CUtensorMapSwizzle, CUtensorMapL2promotion,
    CUtensorMapFloatOOBfill);

extern "C" void kernel_launch(void* const* d_in, const int* in_sizes, int n_in,
                              void* d_out, int out_size) {
    const float* x_in   = (const float*)d_in[0];
    const float* tokens = (const float*)d_in[1];
    const int*   metas  = (const int*)d_in[2];

    float* out     = (float*)d_out;
    float* patches = out;
    float* cx      = out + (size_t)N_PATCHES;
    float* cy      = cx + N_BT;
    float* sc      = cy + N_BT;
    float* fmap    = sc + N_BT;

    static TmapEncodeFn tmap_encode = nullptr;
    if (!tmap_encode) {
        cudaDriverEntryPointQueryResult st;
        cudaGetDriverEntryPointByVersion(
            "cuTensorMapEncodeTiled", (void**)&tmap_encode, 12000,
            cudaEnableDefault, &st);
    }

    CUtensorMap tmap;
    {
        cuuint64_t dims[3]    = {HF_, HF_, (cuuint64_t)B_ * CIN_};
        cuuint64_t strides[2] = {HF_ * 4, (cuuint64_t)HF_ * HF_ * 4};
        cuuint32_t box[3]     = {8, 8, 32};     // 8 cols x 8 rows x 32 cins = 8KB
        cuuint32_t es[3]      = {1, 1, 1};
        tmap_encode(&tmap, CU_TENSOR_MAP_DATA_TYPE_FLOAT32, 3, (void*)x_in,
                    dims, strides, box, es,
                    CU_TENSOR_MAP_INTERLEAVE_NONE, CU_TENSOR_MAP_SWIZZLE_NONE,
                    CU_TENSOR_MAP_L2_PROMOTION_L2_128B,
                    CU_TENSOR_MAP_FLOAT_OOB_FILL_NONE);
    }

    fused_kernel<<<FMAP_BLOCKS + DMA_BLOCKS + N_BT, 256, SMEM_DYN>>>(
        x_in, tokens, metas, patches, cx, cy, sc, fmap, tmap);
}

// round 15
// speedup vs baseline: 1.2322x; 1.1373x over previous
#include <cuda_runtime.h>
#include <cuda.h>
#include <cstdint>

#define B_   8
#define T_   316
#define CIN_ 64
#define HF_  128
#define G_   32
#define E_   384

#define N_PATCHES (B_*T_*CIN_*64)
#define N_BT      (B_*T_)

#define FMAP_BLOCKS  (B_ * G_ * 4)       // (batch, grid-row, e-quarter)
#define EQ_          96
#define SMS_         97

#define IMG_STRIDE4  (HF_ * HF_ / 4)     // float4 stride between cin planes

// per (token, cin-half) crop tile: 32 cins * 8 rows * 8 cols * 4B = 8 KB
#define TILE_BYTES   8192
// dynamic smem must also fit the fmap path: 32*97*4 + 32*4 = 12544
#define SMEM_DYN     13056

// ---------------------------------------------------------------------------
__device__ __forceinline__ uint32_t smem_u32(const void* p) {
    uint32_t a;
    asm("{ .reg .u64 t; cvta.to.shared.u64 t, %1; cvt.u32.u64 %0, t; }"
        : "=r"(a) : "l"(p));
    return a;
}

// ---------------------------------------------------------------------------
// Single fused kernel (R11 structure).
//   blocks [0, FMAP_BLOCKS):        fmap transpose-gather
//   blocks [FMAP_BLOCKS, +2*N_BT):  half-token patch blocks (32 cins each)
//       p==16 : one 3D TMA load (8KB, lands in output layout), then ALL
//               256 threads cooperatively store smem->gmem with __stcs
//               (no bulk-store completion wait on the critical path).
//       p==8  : bilinear compute path (2 float4/thread).
// ---------------------------------------------------------------------------
__global__ void __launch_bounds__(256) fused_kernel(
        const float* __restrict__ x_in,
        const float* __restrict__ tokens,
        const int*   __restrict__ metas,
        float* __restrict__ patches,
        float* __restrict__ cx,
        float* __restrict__ cy,
        float* __restrict__ sc,
        float* __restrict__ fmap,
        const __grid_constant__ CUtensorMap tmap) {

    extern __shared__ char smem_raw[];
    int tid = threadIdx.x;

    if (blockIdx.x >= FMAP_BLOCKS) {
        // --------------------------- patches ---------------------------
        int pid = blockIdx.x - FMAP_BLOCKS;
        int tok = pid >> 1;
        int h   = pid & 1;                 // cin half: 0 -> cins 0..31, 1 -> 32..63
        int b   = tok / T_;

        const int* m = metas + (size_t)tok * 5;
        int r = __ldg(&m[0]), c = __ldg(&m[1]), p = __ldg(&m[3]);

        if (h == 0 && tid == 0) {
            int span = __ldg(&m[2]);
            float hs = 0.5f * (float)span;
            cx[tok] = (float)c + hs;
            cy[tok] = (float)r + hs;
            sc[tok] = (p == 16) ? 1.0f : ((p == 8) ? 2.0f : 0.0f);
        }

        if (p == 16) {
            // -------- TMA load -> cooperative register store --------
            uint32_t sbase = smem_u32(smem_raw);
            uint32_t mbar  = sbase + TILE_BYTES;

            if (tid == 0) {
                asm volatile("mbarrier.init.shared.b64 [%0], 1;"
                             :: "r"(mbar) : "memory");
                asm volatile("fence.proxy.async.shared::cta;" ::: "memory");
                asm volatile("mbarrier.arrive.expect_tx.shared.b64 _, [%0], %1;"
                             :: "r"(mbar), "r"(TILE_BYTES) : "memory");

                int xcoord = c * 4;               // +8 <= 128
                int ycoord = r * 4;               // +8 <= 128
                int zcoord = b * CIN_ + h * 32;   // +32 <= 512
                asm volatile(
                    "cp.async.bulk.tensor.3d.shared::cta.global.tile.mbarrier::complete_tx::bytes "
                    "[%0], [%1, {%2, %3, %4}], [%5];"
                    :: "r"(sbase), "l"(&tmap),
                       "r"(xcoord), "r"(ycoord), "r"(zcoord),
                       "r"(mbar) : "memory");

                // wait for load completion (parity 0)
                asm volatile(
                    "{\n\t"
                    ".reg .pred P1;\n\t"
                    "WAIT_LOOP_%=:\n\t"
                    "mbarrier.try_wait.parity.acquire.cta.shared::cta.b64 P1, [%0], 0, 0x989680;\n\t"
                    "@P1 bra.uni WAIT_DONE_%=;\n\t"
                    "bra.uni WAIT_LOOP_%=;\n\t"
                    "WAIT_DONE_%=:\n\t"
                    "}"
                    :: "r"(mbar) : "memory");
                asm volatile("fence.proxy.async.shared::cta;" ::: "memory");
            }
            __syncthreads();

            // cooperative smem->gmem: 512 float4s, 2 per thread, coalesced.
            // smem layout [cin][i][8 floats] == patches layout: flat copy.
            const float4* s4 = (const float4*)smem_raw;
            float4* gdst = (float4*)((char*)patches +
                           (size_t)tok * 16384 + (size_t)h * TILE_BYTES);
            __stcs(gdst + tid,       s4[tid]);
            __stcs(gdst + tid + 256, s4[tid + 256]);
            return;
        }

        // ----------------------- compute path (p==8 / 0) -----------------------
        // decode (invariant in k): half = bit0, i = bits1-3, cin0 = bits4-7
        int half = tid & 1;
        int i    = (tid >> 1) & 7;
        int cin0 = tid >> 4;               // 0..15 ; cin_local = cin0 + 16k

        const float4* img4 = (const float4*)x_in +
                             ((size_t)b * CIN_ + h * 32 + cin0) * IMG_STRIDE4;
        float4* dst = ((float4*)patches) + (size_t)tok * 1024 + h * 512 + tid;

        if (p > 0) {
            int pf = p >> 1; if (pf < 1) pf = 1;     // <= 4 here
            float pff   = (float)pf;
            float scale = pff * 0.125f;
            float hi    = pff - 1.0f;

            float rel_i = fminf(fmaxf(((float)i + 0.5f) * scale - 0.5f, 0.0f), hi);
            float i0f = floorf(rel_i);
            float wy  = rel_i - i0f;
            float i1f = fminf(i0f + 1.0f, hi);
            int y0off = (r * 4 + (int)i0f) * 32 + c;
            int y1off = (r * 4 + (int)i1f) * 32 + c;

            int   j0[4], j1[4];
            float wx[4];
            #pragma unroll
            for (int jj = 0; jj < 4; jj++) {
                float j = (float)(half * 4 + jj);
                float rel_j = fminf(fmaxf((j + 0.5f) * scale - 0.5f, 0.0f), hi);
                float j0f = floorf(rel_j);
                wx[jj] = rel_j - j0f;
                j0[jj] = (int)j0f;
                int t1 = j0[jj] + 1; if (t1 > (int)hi) t1 = (int)hi;
                j1[jj] = t1;
            }

            float4 t0[2], t1[2];
            #pragma unroll
            for (int k = 0; k < 2; k++) {
                const float4* ik = img4 + (size_t)k * 16 * IMG_STRIDE4;
                t0[k] = __ldg(ik + y0off);
                t1[k] = __ldg(ik + y1off);
            }
            #pragma unroll
            for (int k = 0; k < 2; k++) {
                float rb[4];
                rb[0] = t0[k].x + (t1[k].x - t0[k].x) * wy;
                rb[1] = t0[k].y + (t1[k].y - t0[k].y) * wy;
                rb[2] = t0[k].z + (t1[k].z - t0[k].z) * wy;
                rb[3] = t0[k].w + (t1[k].w - t0[k].w) * wy;
                float4 o;
                o.x = rb[j0[0]] + (rb[j1[0]] - rb[j0[0]]) * wx[0];
                o.y = rb[j0[1]] + (rb[j1[1]] - rb[j0[1]]) * wx[1];
                o.z = rb[j0[2]] + (rb[j1[2]] - rb[j0[2]]) * wx[2];
                o.w = rb[j0[3]] + (rb[j1[3]] - rb[j0[3]]) * wx[3];
                __stcs(dst + k * 256, o);
            }
        } else {
            float4 z = make_float4(0.f, 0.f, 0.f, 0.f);
            __stcs(dst, z);
            __stcs(dst + 256, z);
        }
        return;
    }

    // ----------------------------- fmap -----------------------------
    float* sm    = (float*)smem_raw;                       // 32*SMS_ floats
    int*   s_own = (int*)(smem_raw + 32 * SMS_ * 4);       // 32 ints

    int fb  = blockIdx.x;
    int q   = fb & 3;              // e-quarter
    int row = (fb >> 2) & 31;      // grid row
    int b   = fb >> 7;             // batch
    int lane = tid & 31;
    int w    = tid >> 5;

    // owners for this grid row, from metas (coverage is exact, no races)
    for (int t = tid; t < T_; t += 256) {
        const int* m = metas + (size_t)(b * T_ + t) * 5;
        int r = m[0], c = m[1], span = m[2], p = m[3];
        int di = row - r;
        if (p > 0 && di >= 0 && di < span) {
            for (int dc = 0; dc < span; dc++) {
                int col = c + dc;
                if (col >= 0 && col < G_) s_own[col] = t;
            }
        }
    }
    __syncthreads();

    // phase 1: coalesced token loads -> smem
    int e0 = q * EQ_;
    #pragma unroll
    for (int cc = 0; cc < 4; cc++) {
        int cell = w * 4 + cc;
        const float* src = tokens + ((size_t)(b * T_ + s_own[cell])) * E_ + e0;
        #pragma unroll
        for (int it = 0; it < 3; it++) {
            int e = it * 32 + lane;
            sm[cell * SMS_ + e] = __ldg(&src[e]);
        }
    }
    __syncthreads();

    // phase 2: lane = cell -> fully coalesced 128B stores
    float* dstb = fmap + ((size_t)(b * E_ + e0) + w * 12) * (G_ * G_)
                       + row * 32 + lane;
    #pragma unroll
    for (int k = 0; k < 12; k++)
        __stcs(&dstb[(size_t)k * (G_ * G_)], sm[lane * SMS_ + w * 12 + k]);
}

// ---------------------------------------------------------------------------
typedef CUresult (*TmapEncodeFn)(
    CUtensorMap*, CUtensorMapDataType, cuuint32_t, void*,
    const cuuint64_t*, const cuuint64_t*, const cuuint32_t*, const cuuint32_t*,
    CUtensorMapInterleave, CUtensorMapSwizzle, CUtensorMapL2promotion,
    CUtensorMapFloatOOBfill);

extern "C" void kernel_launch(void* const* d_in, const int* in_sizes, int n_in,
                              void* d_out, int out_size) {
    const float* x_in   = (const float*)d_in[0];
    const float* tokens = (const float*)d_in[1];
    const int*   metas  = (const int*)d_in[2];

    float* out     = (float*)d_out;
    float* patches = out;
    float* cx      = out + (size_t)N_PATCHES;
    float* cy      = cx + N_BT;
    float* sc      = cy + N_BT;
    float* fmap    = sc + N_BT;

    static TmapEncodeFn tmap_encode = nullptr;
    if (!tmap_encode) {
        cudaDriverEntryPointQueryResult st;
        cudaGetDriverEntryPointByVersion(
            "cuTensorMapEncodeTiled", (void**)&tmap_encode, 12000,
            cudaEnableDefault, &st);
    }

    CUtensorMap tmap;
    {
        cuuint64_t dims[3]    = {HF_, HF_, (cuuint64_t)B_ * CIN_};
        cuuint64_t strides[2] = {HF_ * 4, (cuuint64_t)HF_ * HF_ * 4};
        cuuint32_t box[3]     = {8, 8, 32};     // 8 cols x 8 rows x 32 cins = 8KB
        cuuint32_t es[3]      = {1, 1, 1};
        tmap_encode(&tmap, CU_TENSOR_MAP_DATA_TYPE_FLOAT32, 3, (void*)x_in,
                    dims, strides, box, es,
                    CU_TENSOR_MAP_INTERLEAVE_NONE, CU_TENSOR_MAP_SWIZZLE_NONE,
                    CU_TENSOR_MAP_L2_PROMOTION_L2_128B,
                    CU_TENSOR_MAP_FLOAT_OOB_FILL_NONE);
    }

    fused_kernel<<<FMAP_BLOCKS + 2 * N_BT, 256, SMEM_DYN>>>(
        x_in, tokens, metas, patches, cx, cy, sc, fmap, tmap);
}